// round 12
// baseline (speedup 1.0000x reference)
#include <cuda_runtime.h>
#include <cuda_fp16.h>
#include <cstdint>

// ---------------- geometry ----------------
#define NB    8
#define CC    256
#define HH    52
#define WW    52
#define FNO   512
#define HP    54
#define WP    54
#define ROWS_N (HP*WP)          // 2916
#define MGLOB  (NB*ROWS_N)      // 23328
#define OHW    (HH*WW)          // 2704

// ---------------- GEMM tiling ----------------
#define BM 128
#define BN 64
#define BK 32                   // halfs per stage
#define STAGES 3
#define ITERS  72               // 9 taps * (256/32)
#define A_SM   (BM*64)          // 8 KB
#define B_SM   (2*BN*64)        // 8 KB (2 fp16 splits)
#define STG_SM (A_SM + B_SM)    // 16 KB
#define SM_BAR (STAGES*STG_SM)  // 48 KB
#define SMEM_TOTAL (SM_BAR + 128)
#define MTILES ((MGLOB + BM - 1) / BM)   // 183

// prep kernel block ranges
#define QBLKS (16*HH*NB)            // 6656
#define WBLKS ((FNO/32)*(CC/32)*9)  // 1152
#define HBLKS 212

// XOR swizzle: 16B chunk k (0..3) within 64B row r -> conflict-free ldmatrix
#define SWZ(r,k) (((r)<<6) + ((((k) ^ (((r)>>1)&3))) << 4))

// ---------------- device scratch ----------------
__device__ __half g_xh[MGLOB * CC];          // padded NHWC quantized fp16
__device__ __half g_w2[2 * 9 * FNO * CC];    // [split][tap][f][c] fp16

// ---------------- asm helpers ----------------
__device__ __forceinline__ uint32_t smem_u32(const void* p) {
    uint32_t a;
    asm("{ .reg .u64 t; cvta.to.shared.u64 t, %1; cvt.u32.u64 %0, t; }" : "=r"(a) : "l"(p));
    return a;
}
__device__ __forceinline__ void cp16(uint32_t s, const void* g) {
    asm volatile("cp.async.cg.shared.global [%0], [%1], 16;" :: "r"(s), "l"(g));
}
__device__ __forceinline__ void cp_arrive(uint32_t m) {
    asm volatile("cp.async.mbarrier.arrive.noinc.shared.b64 [%0];" :: "r"(m) : "memory");
}
__device__ __forceinline__ void mbar_init(uint32_t m, uint32_t cnt) {
    asm volatile("mbarrier.init.shared.b64 [%0], %1;" :: "r"(m), "r"(cnt) : "memory");
}
__device__ __forceinline__ void mbar_arrive(uint32_t m) {
    asm volatile("mbarrier.arrive.shared.b64 _, [%0];" :: "r"(m) : "memory");
}
__device__ __forceinline__ void mbar_wait(uint32_t m, uint32_t par) {
    asm volatile("{\n\t.reg .pred P;\n\tWL_%=:\n\t"
        "mbarrier.try_wait.parity.shared.b64 P, [%0], %1;\n\t"
        "@P bra.uni WD_%=;\n\tbra.uni WL_%=;\n\tWD_%=:\n\t}"
        :: "r"(m), "r"(par) : "memory");
}
__device__ __forceinline__ void ldsm4(uint32_t& r0, uint32_t& r1, uint32_t& r2, uint32_t& r3,
                                      uint32_t a) {
    asm volatile("ldmatrix.sync.aligned.m8n8.x4.shared.b16 {%0,%1,%2,%3}, [%4];"
                 : "=r"(r0), "=r"(r1), "=r"(r2), "=r"(r3) : "r"(a));
}
__device__ __forceinline__ void mma16816(float* d, const uint32_t* a, const uint32_t* b) {
    asm volatile("mma.sync.aligned.m16n8k16.row.col.f32.f16.f16.f32 "
                 "{%0,%1,%2,%3}, {%4,%5,%6,%7}, {%8,%9}, {%0,%1,%2,%3};"
                 : "+f"(d[0]), "+f"(d[1]), "+f"(d[2]), "+f"(d[3])
                 : "r"(a[0]), "r"(a[1]), "r"(a[2]), "r"(a[3]), "r"(b[0]), "r"(b[1]));
}

// ---------------- fused prep kernel (quant + wprep + halo) ----------------
__global__ __launch_bounds__(256)
void prep_kernel(const float* __restrict__ in, const float* __restrict__ w) {
    const int bid = blockIdx.x;
    const int tid = threadIdx.x;
    const int tx = tid & 31, ty8 = tid >> 5;   // 32 x 8

    if (bid < QBLKS) {
        __shared__ float tile[32][33];
        int xc = bid & 15;
        int y  = (bid >> 4) % HH;
        int n  = bid / (16 * HH);
        int xt = xc & 1, ct = xc >> 1;
        int x = xt * 32 + tx;
#pragma unroll
        for (int j = 0; j < 4; ++j) {
            int c = ct * 32 + ty8 + j * 8;
            if (x < WW) {
                float v = in[((n * CC + c) * HH + y) * WW + x];
                v = rintf(v * 20.0f);
                tile[ty8 + j * 8][tx] = fminf(127.0f, fmaxf(-128.0f, v));
            }
        }
        __syncthreads();
#pragma unroll
        for (int j = 0; j < 4; ++j) {
            int x2 = xt * 32 + ty8 + j * 8;
            int c2 = ct * 32 + tx;
            if (x2 < WW)
                g_xh[((size_t)n * ROWS_N + (y + 1) * WP + (x2 + 1)) * CC + c2] =
                    __float2half_rn(tile[tx][ty8 + j * 8]);
        }
    } else if (bid < QBLKS + WBLKS) {
        __shared__ __half t0[32][33], t1[32][33];
        int b = bid - QBLKS;
        int fb = b & 15;
        int cb = (b >> 4) & 7;
        int tap = b >> 7;
        const int f = fb * 32 + tx;
#pragma unroll
        for (int j = 0; j < 4; ++j) {
            int c = cb * 32 + ty8 + j * 8;
            float v = w[((size_t)c * 9 + tap) * FNO + f];
            __half h0 = __float2half_rn(v);
            float r1 = v - __half2float(h0);
            __half h1 = __float2half_rn(r1);
            t0[ty8 + j * 8][tx] = h0;
            t1[ty8 + j * 8][tx] = h1;
        }
        __syncthreads();
        const size_t sstr = (size_t)9 * FNO * CC;
#pragma unroll
        for (int j = 0; j < 4; ++j) {
            int c2 = cb * 32 + tx;
            int f2 = fb * 32 + ty8 + j * 8;
            size_t base = ((size_t)tap * FNO + f2) * CC + c2;
            g_w2[base]        = t0[tx][ty8 + j * 8];
            g_w2[base + sstr] = t1[tx][ty8 + j * 8];
        }
    } else {
        int idx = (bid - QBLKS - WBLKS) * 256 + tid;
        const int total = NB * 212 * (CC / 8);
        if (idx >= total) return;
        int v = idx & 31;
        int h = (idx >> 5) % 212;
        int n = idx / (212 * 32);
        int y, x;
        if (h < 54)       { y = 0;  x = h; }
        else if (h < 108) { y = 53; x = h - 54; }
        else { int r = h - 108; y = 1 + (r >> 1); x = (r & 1) ? 53 : 0; }
        uint4 z = {0, 0, 0, 0};
        reinterpret_cast<uint4*>(g_xh + ((size_t)n * ROWS_N + y * WP + x) * CC)[v] = z;
    }
}

// ---------------- conv kernel: mma.sync implicit GEMM ------------------------
// 128 threads (4 warps, 2m x 2n of 64x32 warp tiles), 4 CTAs/SM.
// mbarrier-decoupled 3-stage pipeline; early stage release after last ldsm.
__global__ __launch_bounds__(128, 4)
void conv_mma_kernel(const float* __restrict__ bias, float* __restrict__ out) {
    extern __shared__ char smem[];
    const uint32_t sb = smem_u32(smem);
    const int tid  = threadIdx.x;
    const int lane = tid & 31, wid = tid >> 5;
    const int fbase = blockIdx.x * BN;
    const int mbase = blockIdx.y * BM;
    const int wm = (wid & 1) << 6;   // warp m-offset (0/64)
    const int wn = (wid >> 1) << 5;  // warp n-offset (0/32)

    const uint32_t fullb  = sb + SM_BAR;        // count 128 (cp.async noinc)
    const uint32_t emptyb = sb + SM_BAR + 32;   // count 4 (one arrive per warp)
    if (tid == 0) {
#pragma unroll
        for (int s = 0; s < STAGES; ++s) {
            mbar_init(fullb + s * 8, 128);
            mbar_init(emptyb + s * 8, 4);
        }
    }
    __syncthreads();

    float acc[4][4][4];
#pragma unroll
    for (int a = 0; a < 4; ++a)
#pragma unroll
        for (int b = 0; b < 4; ++b)
#pragma unroll
            for (int c = 0; c < 4; ++c) acc[a][b][c] = 0.0f;

    auto issue = [&](int it, int st) {
        const int tap = it >> 3;
        const int c0  = (it & 7) << 5;
        const int taprow = (tap / 3) * WP + (tap % 3);
        const uint32_t sA = sb + (uint32_t)st * STG_SM;
        const uint32_t sB = sA + A_SM;
        // A: 512 chunks (128 rows x 4), 4 per thread
#pragma unroll
        for (int j = 0; j < 4; ++j) {
            int cid = tid + (j << 7);
            int r = cid >> 2, k = cid & 3;
            int grow = mbase + r + taprow;
            if (grow > MGLOB - 1) grow = MGLOB - 1;
            cp16(sA + SWZ(r, k), g_xh + (size_t)grow * CC + c0 + (k << 3));
        }
        // B: 512 chunks (2 splits x 64 rows x 4), 4 per thread
#pragma unroll
        for (int j = 0; j < 4; ++j) {
            int cid = tid + (j << 7);
            int sp = cid >> 8, rem = cid & 255;
            int fr = rem >> 2, k = rem & 3;
            cp16(sB + sp * 4096 + SWZ(fr, k),
                 g_w2 + ((size_t)(sp * 9 + tap) * FNO + fbase + fr) * CC + c0 + (k << 3));
        }
        cp_arrive(fullb + (uint32_t)st * 8);
    };

    issue(0, 0); issue(1, 1);

#pragma unroll 1
    for (int i = 0; i < ITERS; ++i) {
        const int si = i % STAGES;
        const uint32_t sA = sb + (uint32_t)si * STG_SM;
        const uint32_t sB = sA + A_SM;
        mbar_wait(fullb + (uint32_t)si * 8, (i / STAGES) & 1);

        // ---- k16 = 0: loads ----
        uint32_t a0[4][4], b0[2][2][4];
#pragma unroll
        for (int mi = 0; mi < 4; ++mi) {
            int r = wm + (mi << 4) + (lane & 15);
            ldsm4(a0[mi][0], a0[mi][1], a0[mi][2], a0[mi][3],
                  sA + SWZ(r, (lane >> 4)));
        }
#pragma unroll
        for (int sp = 0; sp < 2; ++sp)
#pragma unroll
            for (int nj = 0; nj < 2; ++nj) {
                int r = wn + (nj << 4) + ((lane >> 4) << 3) + (lane & 7);
                ldsm4(b0[sp][nj][0], b0[sp][nj][1], b0[sp][nj][2], b0[sp][nj][3],
                      sB + sp * 4096 + SWZ(r, ((lane >> 3) & 1)));
            }

        // ---- produce stage i+2 in the ldsm latency shadow ----
        int nx = i + 2;
        if (nx < ITERS) {
            int sn = nx % STAGES;
            if (nx >= STAGES)
                mbar_wait(emptyb + (uint32_t)sn * 8, ((nx / STAGES) - 1) & 1);
            issue(nx, sn);
        }

        // ---- k16 = 0: MMAs ----
#pragma unroll
        for (int sp = 0; sp < 2; ++sp)
#pragma unroll
            for (int nj = 0; nj < 2; ++nj)
#pragma unroll
                for (int mi = 0; mi < 4; ++mi) {
                    mma16816(acc[mi][nj * 2],     a0[mi], b0[sp][nj]);
                    mma16816(acc[mi][nj * 2 + 1], a0[mi], b0[sp][nj] + 2);
                }

        // ---- k16 = 1: loads, EARLY release, MMAs ----
        uint32_t a1[4][4], b1[2][2][4];
#pragma unroll
        for (int mi = 0; mi < 4; ++mi) {
            int r = wm + (mi << 4) + (lane & 15);
            ldsm4(a1[mi][0], a1[mi][1], a1[mi][2], a1[mi][3],
                  sA + SWZ(r, 2 + (lane >> 4)));
        }
#pragma unroll
        for (int sp = 0; sp < 2; ++sp)
#pragma unroll
            for (int nj = 0; nj < 2; ++nj) {
                int r = wn + (nj << 4) + ((lane >> 4) << 3) + (lane & 7);
                ldsm4(b1[sp][nj][0], b1[sp][nj][1], b1[sp][nj][2], b1[sp][nj][3],
                      sB + sp * 4096 + SWZ(r, 2 + ((lane >> 3) & 1)));
            }
        if (lane == 0)
            mbar_arrive(emptyb + (uint32_t)si * 8);
#pragma unroll
        for (int sp = 0; sp < 2; ++sp)
#pragma unroll
            for (int nj = 0; nj < 2; ++nj)
#pragma unroll
                for (int mi = 0; mi < 4; ++mi) {
                    mma16816(acc[mi][nj * 2],     a1[mi], b1[sp][nj]);
                    mma16816(acc[mi][nj * 2 + 1], a1[mi], b1[sp][nj] + 2);
                }
    }

    // ---------------- epilogue: clip(round(0.25*acc + 4*bias)) -> NCHW -------
    float bv[4][2];
#pragma unroll
    for (int nj2 = 0; nj2 < 4; ++nj2)
#pragma unroll
        for (int e = 0; e < 2; ++e)
            bv[nj2][e] = bias[fbase + wn + nj2 * 8 + ((lane & 3) << 1) + e] * 4.0f;

#pragma unroll
    for (int mi = 0; mi < 4; ++mi) {
        int m0 = mbase + wm + (mi << 4) + (lane >> 2);
#pragma unroll
        for (int half = 0; half < 2; ++half) {
            int g = m0 + half * 8;
            int n_img = g / ROWS_N;
            int rr = g - n_img * ROWS_N;
            int y = rr / WP;
            int x = rr - y * WP;
            bool valid = (g < MGLOB) && (y < HH) && (x < WW);
            float* ob = valid ? (out + ((size_t)n_img * FNO) * OHW + y * WW + x) : out;
#pragma unroll
            for (int nj2 = 0; nj2 < 4; ++nj2) {
#pragma unroll
                for (int e = 0; e < 2; ++e) {
                    int f = fbase + wn + nj2 * 8 + ((lane & 3) << 1) + e;
                    float v = acc[mi][nj2][half * 2 + e] * 0.25f + bv[nj2][e];
                    v = rintf(v);
                    v = fminf(127.0f, fmaxf(-128.0f, v));
                    if (valid) ob[(size_t)f * OHW] = v;
                }
            }
        }
    }
}

// ---------------- host ----------------
extern "C" void kernel_launch(void* const* d_in, const int* in_sizes, int n_in,
                              void* d_out, int out_size) {
    const float* in_data = (const float*)d_in[0];
    const float* weight  = (const float*)d_in[1];
    const float* bias    = (const float*)d_in[2];
    float* out = (float*)d_out;

    cudaFuncSetAttribute(conv_mma_kernel, cudaFuncAttributeMaxDynamicSharedMemorySize,
                         SMEM_TOTAL);

    prep_kernel<<<QBLKS + WBLKS + HBLKS, 256>>>(in_data, weight);
    {
        dim3 grid(FNO / BN, MTILES);   // (8, 183) = 1464
        conv_mma_kernel<<<grid, 128, SMEM_TOTAL>>>(bias, out);
    }
}

// round 13
// speedup vs baseline: 1.0322x; 1.0322x over previous
#include <cuda_runtime.h>
#include <cuda_fp16.h>
#include <cstdint>

// ---------------- geometry ----------------
#define NB    8
#define CC    256
#define HH    52
#define WW    52
#define FNO   512
#define HP    54
#define WP    54
#define ROWS_N (HP*WP)          // 2916 padded raster rows per image
#define MGLOB  (NB*ROWS_N)      // 23328 (padded buffer rows)
#define OHW    (HH*WW)          // 2704
#define MCOMP  (NB*OHW)         // 21632 compact GEMM rows (all real outputs)

// ---------------- GEMM tiling ----------------
#define BM 128
#define BN 128
#define BK 32                   // halfs per stage
#define STAGES 4
#define ITERS  72               // 9 taps * (256/32)
#define A_SM   (BM*64)          // 8 KB
#define B_SM   (2*BN*64)        // 16 KB (2 fp16 splits)
#define STG_SM (A_SM + B_SM)    // 24 KB
#define SM_BAR (STAGES*STG_SM)  // 96 KB
#define SMEM_TOTAL (SM_BAR + 128)
#define MTILES (MCOMP / BM)     // 169 exact

// prep kernel block ranges
#define QBLKS (16*HH*NB)            // 6656
#define WBLKS ((FNO/32)*(CC/32)*9)  // 1152
#define HBLKS 212

// XOR swizzle: 16B chunk k (0..3) within 64B row r -> conflict-free ldmatrix
#define SWZ(r,k) (((r)<<6) + ((((k) ^ (((r)>>1)&3))) << 4))

// ---------------- device scratch ----------------
__device__ __half g_xh[MGLOB * CC];          // padded NHWC quantized fp16
__device__ __half g_w2[2 * 9 * FNO * CC];    // [split][tap][f][c] fp16

// ---------------- asm helpers ----------------
__device__ __forceinline__ uint32_t smem_u32(const void* p) {
    uint32_t a;
    asm("{ .reg .u64 t; cvta.to.shared.u64 t, %1; cvt.u32.u64 %0, t; }" : "=r"(a) : "l"(p));
    return a;
}
__device__ __forceinline__ void cp16(uint32_t s, const void* g) {
    asm volatile("cp.async.cg.shared.global [%0], [%1], 16;" :: "r"(s), "l"(g));
}
__device__ __forceinline__ void cp_arrive(uint32_t m) {
    asm volatile("cp.async.mbarrier.arrive.noinc.shared.b64 [%0];" :: "r"(m) : "memory");
}
__device__ __forceinline__ void mbar_init(uint32_t m, uint32_t cnt) {
    asm volatile("mbarrier.init.shared.b64 [%0], %1;" :: "r"(m), "r"(cnt) : "memory");
}
__device__ __forceinline__ void mbar_arrive(uint32_t m) {
    asm volatile("mbarrier.arrive.shared.b64 _, [%0];" :: "r"(m) : "memory");
}
__device__ __forceinline__ void mbar_wait(uint32_t m, uint32_t par) {
    asm volatile("{\n\t.reg .pred P;\n\tWL_%=:\n\t"
        "mbarrier.try_wait.parity.shared.b64 P, [%0], %1;\n\t"
        "@P bra.uni WD_%=;\n\tbra.uni WL_%=;\n\tWD_%=:\n\t}"
        :: "r"(m), "r"(par) : "memory");
}
__device__ __forceinline__ void ldsm4(uint32_t& r0, uint32_t& r1, uint32_t& r2, uint32_t& r3,
                                      uint32_t a) {
    asm volatile("ldmatrix.sync.aligned.m8n8.x4.shared.b16 {%0,%1,%2,%3}, [%4];"
                 : "=r"(r0), "=r"(r1), "=r"(r2), "=r"(r3) : "r"(a));
}
__device__ __forceinline__ void mma16816(float* d, const uint32_t* a, const uint32_t* b) {
    asm volatile("mma.sync.aligned.m16n8k16.row.col.f32.f16.f16.f32 "
                 "{%0,%1,%2,%3}, {%4,%5,%6,%7}, {%8,%9}, {%0,%1,%2,%3};"
                 : "+f"(d[0]), "+f"(d[1]), "+f"(d[2]), "+f"(d[3])
                 : "r"(a[0]), "r"(a[1]), "r"(a[2]), "r"(a[3]), "r"(b[0]), "r"(b[1]));
}

// ---------------- fused prep kernel (quant + wprep + halo) ----------------
__global__ __launch_bounds__(256)
void prep_kernel(const float* __restrict__ in, const float* __restrict__ w) {
    const int bid = blockIdx.x;
    const int tid = threadIdx.x;
    const int tx = tid & 31, ty8 = tid >> 5;   // 32 x 8

    if (bid < QBLKS) {
        __shared__ float tile[32][33];
        int xc = bid & 15;
        int y  = (bid >> 4) % HH;
        int n  = bid / (16 * HH);
        int xt = xc & 1, ct = xc >> 1;
        int x = xt * 32 + tx;
#pragma unroll
        for (int j = 0; j < 4; ++j) {
            int c = ct * 32 + ty8 + j * 8;
            if (x < WW) {
                float v = in[((n * CC + c) * HH + y) * WW + x];
                v = rintf(v * 20.0f);
                tile[ty8 + j * 8][tx] = fminf(127.0f, fmaxf(-128.0f, v));
            }
        }
        __syncthreads();
#pragma unroll
        for (int j = 0; j < 4; ++j) {
            int x2 = xt * 32 + ty8 + j * 8;
            int c2 = ct * 32 + tx;
            if (x2 < WW)
                g_xh[((size_t)n * ROWS_N + (y + 1) * WP + (x2 + 1)) * CC + c2] =
                    __float2half_rn(tile[tx][ty8 + j * 8]);
        }
    } else if (bid < QBLKS + WBLKS) {
        __shared__ __half t0[32][33], t1[32][33];
        int b = bid - QBLKS;
        int fb = b & 15;
        int cb = (b >> 4) & 7;
        int tap = b >> 7;
        const int f = fb * 32 + tx;
#pragma unroll
        for (int j = 0; j < 4; ++j) {
            int c = cb * 32 + ty8 + j * 8;
            float v = w[((size_t)c * 9 + tap) * FNO + f];
            __half h0 = __float2half_rn(v);
            float r1 = v - __half2float(h0);
            __half h1 = __float2half_rn(r1);
            t0[ty8 + j * 8][tx] = h0;
            t1[ty8 + j * 8][tx] = h1;
        }
        __syncthreads();
        const size_t sstr = (size_t)9 * FNO * CC;
#pragma unroll
        for (int j = 0; j < 4; ++j) {
            int c2 = cb * 32 + tx;
            int f2 = fb * 32 + ty8 + j * 8;
            size_t base = ((size_t)tap * FNO + f2) * CC + c2;
            g_w2[base]        = t0[tx][ty8 + j * 8];
            g_w2[base + sstr] = t1[tx][ty8 + j * 8];
        }
    } else {
        int idx = (bid - QBLKS - WBLKS) * 256 + tid;
        const int total = NB * 212 * (CC / 8);
        if (idx >= total) return;
        int v = idx & 31;
        int h = (idx >> 5) % 212;
        int n = idx / (212 * 32);
        int y, x;
        if (h < 54)       { y = 0;  x = h; }
        else if (h < 108) { y = 53; x = h - 54; }
        else { int r = h - 108; y = 1 + (r >> 1); x = (r & 1) ? 53 : 0; }
        uint4 z = {0, 0, 0, 0};
        reinterpret_cast<uint4*>(g_xh + ((size_t)n * ROWS_N + y * WP + x) * CC)[v] = z;
    }
}

// ---------------- conv kernel: mma.sync implicit GEMM ------------------------
// 256 threads (8 warps, 2m x 4n of 64x32 warp tiles), 2 CTAs/SM.
// COMPACT M: every GEMM row is a real output pixel (no halo waste).
// mbarrier-decoupled 4-stage pipeline; early stage release after last ldsm.
__global__ __launch_bounds__(256, 2)
void conv_mma_kernel(const float* __restrict__ bias, float* __restrict__ out) {
    extern __shared__ char smem[];
    const uint32_t sb = smem_u32(smem);
    const int tid  = threadIdx.x;
    const int lane = tid & 31, wid = tid >> 5;
    const int fbase = blockIdx.x * BN;
    const int mbase = blockIdx.y * BM;
    const int wm = (wid & 1) << 6;   // warp m-offset (0/64)
    const int wn = (wid >> 1) << 5;  // warp n-offset (0/32/64/96)

    const uint32_t fullb  = sb + SM_BAR;        // count 256 (cp.async noinc)
    const uint32_t emptyb = sb + SM_BAR + 32;   // count 8 (one arrive per warp)
    if (tid == 0) {
#pragma unroll
        for (int s = 0; s < STAGES; ++s) {
            mbar_init(fullb + s * 8, 256);
            mbar_init(emptyb + s * 8, 8);
        }
    }
    __syncthreads();

    // per-thread A-loader row mapping (loop-invariant): compact m -> padded raster
    int arow[2];
#pragma unroll
    for (int j = 0; j < 2; ++j) {
        int r = (tid + (j << 8)) >> 2;          // tile row 0..127
        int m = mbase + r;                      // compact row, < MCOMP
        int n = m / OHW;
        int rem = m - n * OHW;
        int y = rem / WW;
        int x = rem - y * WW;
        arow[j] = n * ROWS_N + y * WP + x;      // tap 0 source row in padded buffer
    }

    float acc[4][4][4];
#pragma unroll
    for (int a = 0; a < 4; ++a)
#pragma unroll
        for (int b = 0; b < 4; ++b)
#pragma unroll
            for (int c = 0; c < 4; ++c) acc[a][b][c] = 0.0f;

    auto issue = [&](int it) {
        const int tap = it >> 3;
        const int c0  = (it & 7) << 5;
        const int taprow = (tap / 3) * WP + (tap % 3);
        const uint32_t sA = sb + (uint32_t)(it & (STAGES - 1)) * STG_SM;
        const uint32_t sB = sA + A_SM;
#pragma unroll
        for (int j = 0; j < 2; ++j) {
            int cid = tid + (j << 8);
            int r = cid >> 2, k = cid & 3;
            cp16(sA + SWZ(r, k),
                 g_xh + (size_t)(arow[j] + taprow) * CC + c0 + (k << 3));
        }
#pragma unroll
        for (int j = 0; j < 4; ++j) {
            int cid = tid + (j << 8);
            int sp = cid >> 9, rem = cid & 511;
            int fr = rem >> 2, k = rem & 3;
            cp16(sB + sp * 8192 + SWZ(fr, k),
                 g_w2 + ((size_t)(sp * 9 + tap) * FNO + fbase + fr) * CC + c0 + (k << 3));
        }
        cp_arrive(fullb + (uint32_t)(it & (STAGES - 1)) * 8);
    };

    issue(0); issue(1); issue(2);

#pragma unroll 1
    for (int i = 0; i < ITERS; ++i) {
        const uint32_t sA = sb + (uint32_t)(i & (STAGES - 1)) * STG_SM;
        const uint32_t sB = sA + A_SM;
        mbar_wait(fullb + (uint32_t)(i & (STAGES - 1)) * 8, (i >> 2) & 1);

        // ---- k16 = 0: loads ----
        uint32_t a0[4][4], b0[2][2][4];
#pragma unroll
        for (int mi = 0; mi < 4; ++mi) {
            int r = wm + (mi << 4) + (lane & 15);
            ldsm4(a0[mi][0], a0[mi][1], a0[mi][2], a0[mi][3],
                  sA + SWZ(r, (lane >> 4)));
        }
#pragma unroll
        for (int sp = 0; sp < 2; ++sp)
#pragma unroll
            for (int nj = 0; nj < 2; ++nj) {
                int r = wn + (nj << 4) + ((lane >> 4) << 3) + (lane & 7);
                ldsm4(b0[sp][nj][0], b0[sp][nj][1], b0[sp][nj][2], b0[sp][nj][3],
                      sB + sp * 8192 + SWZ(r, ((lane >> 3) & 1)));
            }

        // ---- produce stage i+3 in the ldsm latency shadow ----
        int nx = i + 3;
        if (nx < ITERS) {
            if (nx >= STAGES)
                mbar_wait(emptyb + (uint32_t)(nx & (STAGES - 1)) * 8,
                          ((nx >> 2) - 1) & 1);
            issue(nx);
        }

        // ---- k16 = 0: MMAs ----
#pragma unroll
        for (int sp = 0; sp < 2; ++sp)
#pragma unroll
            for (int nj = 0; nj < 2; ++nj)
#pragma unroll
                for (int mi = 0; mi < 4; ++mi) {
                    mma16816(acc[mi][nj * 2],     a0[mi], b0[sp][nj]);
                    mma16816(acc[mi][nj * 2 + 1], a0[mi], b0[sp][nj] + 2);
                }

        // ---- k16 = 1: loads, EARLY release, MMAs ----
        uint32_t a1[4][4], b1[2][2][4];
#pragma unroll
        for (int mi = 0; mi < 4; ++mi) {
            int r = wm + (mi << 4) + (lane & 15);
            ldsm4(a1[mi][0], a1[mi][1], a1[mi][2], a1[mi][3],
                  sA + SWZ(r, 2 + (lane >> 4)));
        }
#pragma unroll
        for (int sp = 0; sp < 2; ++sp)
#pragma unroll
            for (int nj = 0; nj < 2; ++nj) {
                int r = wn + (nj << 4) + ((lane >> 4) << 3) + (lane & 7);
                ldsm4(b1[sp][nj][0], b1[sp][nj][1], b1[sp][nj][2], b1[sp][nj][3],
                      sB + sp * 8192 + SWZ(r, 2 + ((lane >> 3) & 1)));
            }
        if (lane == 0)
            mbar_arrive(emptyb + (uint32_t)(i & (STAGES - 1)) * 8);
#pragma unroll
        for (int sp = 0; sp < 2; ++sp)
#pragma unroll
            for (int nj = 0; nj < 2; ++nj)
#pragma unroll
                for (int mi = 0; mi < 4; ++mi) {
                    mma16816(acc[mi][nj * 2],     a1[mi], b1[sp][nj]);
                    mma16816(acc[mi][nj * 2 + 1], a1[mi], b1[sp][nj] + 2);
                }
    }

    // ---------------- epilogue: clip(round(0.25*acc + 4*bias)) -> NCHW -------
    // All rows valid (compact M): no predicates.
    float bv[4][2];
#pragma unroll
    for (int nj2 = 0; nj2 < 4; ++nj2)
#pragma unroll
        for (int e = 0; e < 2; ++e)
            bv[nj2][e] = bias[fbase + wn + nj2 * 8 + ((lane & 3) << 1) + e] * 4.0f;

#pragma unroll
    for (int mi = 0; mi < 4; ++mi) {
        int m0 = mbase + wm + (mi << 4) + (lane >> 2);
#pragma unroll
        for (int half = 0; half < 2; ++half) {
            int g = m0 + half * 8;
            int n_img = g / OHW;
            int rem = g - n_img * OHW;       // = y*52 + x, already output raster
            float* ob = out + (size_t)n_img * FNO * OHW + rem;
#pragma unroll
            for (int nj2 = 0; nj2 < 4; ++nj2) {
#pragma unroll
                for (int e = 0; e < 2; ++e) {
                    int f = fbase + wn + nj2 * 8 + ((lane & 3) << 1) + e;
                    float v = acc[mi][nj2][half * 2 + e] * 0.25f + bv[nj2][e];
                    v = rintf(v);
                    v = fminf(127.0f, fmaxf(-128.0f, v));
                    ob[(size_t)f * OHW] = v;
                }
            }
        }
    }
}

// ---------------- host ----------------
extern "C" void kernel_launch(void* const* d_in, const int* in_sizes, int n_in,
                              void* d_out, int out_size) {
    const float* in_data = (const float*)d_in[0];
    const float* weight  = (const float*)d_in[1];
    const float* bias    = (const float*)d_in[2];
    float* out = (float*)d_out;

    cudaFuncSetAttribute(conv_mma_kernel, cudaFuncAttributeMaxDynamicSharedMemorySize,
                         SMEM_TOTAL);

    prep_kernel<<<QBLKS + WBLKS + HBLKS, 256>>>(in_data, weight);
    {
        dim3 grid(FNO / BN, MTILES);   // (4, 169) = 676 CTAs
        conv_mma_kernel<<<grid, 256, SMEM_TOTAL>>>(bias, out);
    }
}

// round 14
// speedup vs baseline: 1.0612x; 1.0281x over previous
#include <cuda_runtime.h>
#include <cuda_fp16.h>
#include <cstdint>

// ---------------- geometry ----------------
#define NB    8
#define CC    256
#define HH    52
#define WW    52
#define FNO   512
#define HP    54
#define WP    54
#define ROWS_N (HP*WP)          // 2916 padded raster rows per image
#define MGLOB  (NB*ROWS_N)      // 23328 (padded buffer rows)
#define OHW    (HH*WW)          // 2704
#define MCOMP  (NB*OHW)         // 21632 compact GEMM rows

// ---------------- GEMM tiling ----------------
#define BM 128
#define BN 128
#define BK 64                   // halfs per stage (two 32-chunk sub-blocks)
#define STAGES 2
#define ITERS  36               // 9 taps * (256/64)
// stage layout: [A sub0 8K][A sub1 8K][B sub0 16K][B sub1 16K] = 48 KB
#define STG_SM 49152
#define SM_BAR (STAGES*STG_SM)  // 96 KB
#define SMEM_TOTAL (SM_BAR + 128)
#define MTILES (MCOMP / BM)     // 169 exact

// prep kernel block ranges
#define QBLKS (16*HH*NB)            // 6656
#define WBLKS ((FNO/32)*(CC/32)*9)  // 1152
#define HBLKS 212

// XOR swizzle: 16B chunk k (0..3) within 64B row r -> conflict-free ldmatrix
#define SWZ(r,k) (((r)<<6) + ((((k) ^ (((r)>>1)&3))) << 4))

// ---------------- device scratch ----------------
__device__ __half g_xh[MGLOB * CC];          // padded NHWC quantized fp16
__device__ __half g_w2[2 * 9 * FNO * CC];    // [split][tap][f][c] fp16

// ---------------- asm helpers ----------------
__device__ __forceinline__ uint32_t smem_u32(const void* p) {
    uint32_t a;
    asm("{ .reg .u64 t; cvta.to.shared.u64 t, %1; cvt.u32.u64 %0, t; }" : "=r"(a) : "l"(p));
    return a;
}
__device__ __forceinline__ void cp16(uint32_t s, const void* g) {
    asm volatile("cp.async.cg.shared.global [%0], [%1], 16;" :: "r"(s), "l"(g));
}
__device__ __forceinline__ void cp_arrive(uint32_t m) {
    asm volatile("cp.async.mbarrier.arrive.noinc.shared.b64 [%0];" :: "r"(m) : "memory");
}
__device__ __forceinline__ void mbar_init(uint32_t m, uint32_t cnt) {
    asm volatile("mbarrier.init.shared.b64 [%0], %1;" :: "r"(m), "r"(cnt) : "memory");
}
__device__ __forceinline__ void mbar_arrive(uint32_t m) {
    asm volatile("mbarrier.arrive.shared.b64 _, [%0];" :: "r"(m) : "memory");
}
__device__ __forceinline__ void mbar_wait(uint32_t m, uint32_t par) {
    asm volatile("{\n\t.reg .pred P;\n\tWL_%=:\n\t"
        "mbarrier.try_wait.parity.shared.b64 P, [%0], %1;\n\t"
        "@P bra.uni WD_%=;\n\tbra.uni WL_%=;\n\tWD_%=:\n\t}"
        :: "r"(m), "r"(par) : "memory");
}
__device__ __forceinline__ void ldsm4(uint32_t& r0, uint32_t& r1, uint32_t& r2, uint32_t& r3,
                                      uint32_t a) {
    asm volatile("ldmatrix.sync.aligned.m8n8.x4.shared.b16 {%0,%1,%2,%3}, [%4];"
                 : "=r"(r0), "=r"(r1), "=r"(r2), "=r"(r3) : "r"(a));
}
__device__ __forceinline__ void mma16816(float* d, const uint32_t* a, const uint32_t* b) {
    asm volatile("mma.sync.aligned.m16n8k16.row.col.f32.f16.f16.f32 "
                 "{%0,%1,%2,%3}, {%4,%5,%6,%7}, {%8,%9}, {%0,%1,%2,%3};"
                 : "+f"(d[0]), "+f"(d[1]), "+f"(d[2]), "+f"(d[3])
                 : "r"(a[0]), "r"(a[1]), "r"(a[2]), "r"(a[3]), "r"(b[0]), "r"(b[1]));
}

// ---------------- fused prep kernel (quant + wprep + halo) ----------------
__global__ __launch_bounds__(256)
void prep_kernel(const float* __restrict__ in, const float* __restrict__ w) {
    const int bid = blockIdx.x;
    const int tid = threadIdx.x;
    const int tx = tid & 31, ty8 = tid >> 5;   // 32 x 8

    if (bid < QBLKS) {
        __shared__ float tile[32][33];
        int xc = bid & 15;
        int y  = (bid >> 4) % HH;
        int n  = bid / (16 * HH);
        int xt = xc & 1, ct = xc >> 1;
        int x = xt * 32 + tx;
#pragma unroll
        for (int j = 0; j < 4; ++j) {
            int c = ct * 32 + ty8 + j * 8;
            if (x < WW) {
                float v = in[((n * CC + c) * HH + y) * WW + x];
                v = rintf(v * 20.0f);
                tile[ty8 + j * 8][tx] = fminf(127.0f, fmaxf(-128.0f, v));
            }
        }
        __syncthreads();
#pragma unroll
        for (int j = 0; j < 4; ++j) {
            int x2 = xt * 32 + ty8 + j * 8;
            int c2 = ct * 32 + tx;
            if (x2 < WW)
                g_xh[((size_t)n * ROWS_N + (y + 1) * WP + (x2 + 1)) * CC + c2] =
                    __float2half_rn(tile[tx][ty8 + j * 8]);
        }
    } else if (bid < QBLKS + WBLKS) {
        __shared__ __half t0[32][33], t1[32][33];
        int b = bid - QBLKS;
        int fb = b & 15;
        int cb = (b >> 4) & 7;
        int tap = b >> 7;
        const int f = fb * 32 + tx;
#pragma unroll
        for (int j = 0; j < 4; ++j) {
            int c = cb * 32 + ty8 + j * 8;
            float v = w[((size_t)c * 9 + tap) * FNO + f];
            __half h0 = __float2half_rn(v);
            float r1 = v - __half2float(h0);
            __half h1 = __float2half_rn(r1);
            t0[ty8 + j * 8][tx] = h0;
            t1[ty8 + j * 8][tx] = h1;
        }
        __syncthreads();
        const size_t sstr = (size_t)9 * FNO * CC;
#pragma unroll
        for (int j = 0; j < 4; ++j) {
            int c2 = cb * 32 + tx;
            int f2 = fb * 32 + ty8 + j * 8;
            size_t base = ((size_t)tap * FNO + f2) * CC + c2;
            g_w2[base]        = t0[tx][ty8 + j * 8];
            g_w2[base + sstr] = t1[tx][ty8 + j * 8];
        }
    } else {
        int idx = (bid - QBLKS - WBLKS) * 256 + tid;
        const int total = NB * 212 * (CC / 8);
        if (idx >= total) return;
        int v = idx & 31;
        int h = (idx >> 5) % 212;
        int n = idx / (212 * 32);
        int y, x;
        if (h < 54)       { y = 0;  x = h; }
        else if (h < 108) { y = 53; x = h - 54; }
        else { int r = h - 108; y = 1 + (r >> 1); x = (r & 1) ? 53 : 0; }
        uint4 z = {0, 0, 0, 0};
        reinterpret_cast<uint4*>(g_xh + ((size_t)n * ROWS_N + y * WP + x) * CC)[v] = z;
    }
}

// ---------------- conv kernel: mma.sync implicit GEMM ------------------------
// 256 threads (8 warps, 2m x 4n of 64x32 warp tiles), 2 CTAs/SM.
// BK=64 stages, 2-stage mbarrier pipeline (lead 1): half the barrier events
// per HMMA vs BK=32/4-stage. Compact M (all rows real outputs).
__global__ __launch_bounds__(256, 2)
void conv_mma_kernel(const float* __restrict__ bias, float* __restrict__ out) {
    extern __shared__ char smem[];
    const uint32_t sb = smem_u32(smem);
    const int tid  = threadIdx.x;
    const int lane = tid & 31, wid = tid >> 5;
    const int fbase = blockIdx.x * BN;
    const int mbase = blockIdx.y * BM;
    const int wm = (wid & 1) << 6;   // warp m-offset (0/64)
    const int wn = (wid >> 1) << 5;  // warp n-offset (0/32/64/96)

    const uint32_t fullb  = sb + SM_BAR;        // count 256 (cp.async noinc)
    const uint32_t emptyb = sb + SM_BAR + 32;   // count 8 (one arrive per warp)
    if (tid == 0) {
#pragma unroll
        for (int s = 0; s < STAGES; ++s) {
            mbar_init(fullb + s * 8, 256);
            mbar_init(emptyb + s * 8, 8);
        }
    }
    __syncthreads();

    // per-thread A-loader row mapping (loop-invariant): compact m -> padded raster
    int arow[2];
#pragma unroll
    for (int j = 0; j < 2; ++j) {
        int r = (tid + (j << 8)) >> 2;          // tile row 0..127
        int m = mbase + r;
        int n = m / OHW;
        int rem = m - n * OHW;
        int y = rem / WW;
        int x = rem - y * WW;
        arow[j] = n * ROWS_N + y * WP + x;
    }

    float acc[4][4][4];
#pragma unroll
    for (int a = 0; a < 4; ++a)
#pragma unroll
        for (int b = 0; b < 4; ++b)
#pragma unroll
            for (int c = 0; c < 4; ++c) acc[a][b][c] = 0.0f;

    // fill stage (it&1) with 64 channels starting at tap/(it&3)*64
    auto issue = [&](int it) {
        const int tap = it >> 2;
        const int c0  = (it & 3) << 6;
        const int taprow = (tap / 3) * WP + (tap % 3);
        const uint32_t st = sb + (uint32_t)(it & 1) * STG_SM;
#pragma unroll
        for (int c01 = 0; c01 < 2; ++c01) {
            const int cc = c0 + (c01 << 5);
            const uint32_t sA = st + (uint32_t)c01 * 8192;
            const uint32_t sB = st + 16384 + (uint32_t)c01 * 16384;
#pragma unroll
            for (int j = 0; j < 2; ++j) {
                int cid = tid + (j << 8);
                int r = cid >> 2, k = cid & 3;
                cp16(sA + SWZ(r, k),
                     g_xh + (size_t)(arow[j] + taprow) * CC + cc + (k << 3));
            }
#pragma unroll
            for (int j = 0; j < 4; ++j) {
                int cid = tid + (j << 8);
                int sp = cid >> 9, rem = cid & 511;
                int fr = rem >> 2, k = rem & 3;
                cp16(sB + sp * 8192 + SWZ(fr, k),
                     g_w2 + ((size_t)(sp * 9 + tap) * FNO + fbase + fr) * CC + cc + (k << 3));
            }
        }
        cp_arrive(fullb + (uint32_t)(it & 1) * 8);
    };

    issue(0);   // lead-1 prologue

#pragma unroll 1
    for (int i = 0; i < ITERS; ++i) {
        const uint32_t st = sb + (uint32_t)(i & 1) * STG_SM;
        mbar_wait(fullb + (uint32_t)(i & 1) * 8, (i >> 1) & 1);

#pragma unroll
        for (int c01 = 0; c01 < 2; ++c01) {
            const uint32_t sA = st + (uint32_t)c01 * 8192;
            const uint32_t sB = st + 16384 + (uint32_t)c01 * 16384;

            // ---- k16 = 0: loads ----
            uint32_t a0[4][4], b0[2][2][4];
#pragma unroll
            for (int mi = 0; mi < 4; ++mi) {
                int r = wm + (mi << 4) + (lane & 15);
                ldsm4(a0[mi][0], a0[mi][1], a0[mi][2], a0[mi][3],
                      sA + SWZ(r, (lane >> 4)));
            }
#pragma unroll
            for (int sp = 0; sp < 2; ++sp)
#pragma unroll
                for (int nj = 0; nj < 2; ++nj) {
                    int r = wn + (nj << 4) + ((lane >> 4) << 3) + (lane & 7);
                    ldsm4(b0[sp][nj][0], b0[sp][nj][1], b0[sp][nj][2], b0[sp][nj][3],
                          sB + sp * 8192 + SWZ(r, ((lane >> 3) & 1)));
                }

            // ---- produce next stage in the first ldsm shadow ----
            if (c01 == 0) {
                int nx = i + 1;
                if (nx < ITERS) {
                    if (nx >= 2)
                        mbar_wait(emptyb + (uint32_t)(nx & 1) * 8,
                                  ((nx >> 1) - 1) & 1);
                    issue(nx);
                }
            }

            // ---- k16 = 0: MMAs ----
#pragma unroll
            for (int sp = 0; sp < 2; ++sp)
#pragma unroll
                for (int nj = 0; nj < 2; ++nj)
#pragma unroll
                    for (int mi = 0; mi < 4; ++mi) {
                        mma16816(acc[mi][nj * 2],     a0[mi], b0[sp][nj]);
                        mma16816(acc[mi][nj * 2 + 1], a0[mi], b0[sp][nj] + 2);
                    }

            // ---- k16 = 1: loads, (early release on last block), MMAs ----
            uint32_t a1[4][4], b1[2][2][4];
#pragma unroll
            for (int mi = 0; mi < 4; ++mi) {
                int r = wm + (mi << 4) + (lane & 15);
                ldsm4(a1[mi][0], a1[mi][1], a1[mi][2], a1[mi][3],
                      sA + SWZ(r, 2 + (lane >> 4)));
            }
#pragma unroll
            for (int sp = 0; sp < 2; ++sp)
#pragma unroll
                for (int nj = 0; nj < 2; ++nj) {
                    int r = wn + (nj << 4) + ((lane >> 4) << 3) + (lane & 7);
                    ldsm4(b1[sp][nj][0], b1[sp][nj][1], b1[sp][nj][2], b1[sp][nj][3],
                          sB + sp * 8192 + SWZ(r, 2 + ((lane >> 3) & 1)));
                }
            if (c01 == 1 && lane == 0)
                mbar_arrive(emptyb + (uint32_t)(i & 1) * 8);
#pragma unroll
            for (int sp = 0; sp < 2; ++sp)
#pragma unroll
                for (int nj = 0; nj < 2; ++nj)
#pragma unroll
                    for (int mi = 0; mi < 4; ++mi) {
                        mma16816(acc[mi][nj * 2],     a1[mi], b1[sp][nj]);
                        mma16816(acc[mi][nj * 2 + 1], a1[mi], b1[sp][nj] + 2);
                    }
        }
    }

    // ---------------- epilogue: clip(round(0.25*acc + 4*bias)) -> NCHW -------
    float bv[4][2];
#pragma unroll
    for (int nj2 = 0; nj2 < 4; ++nj2)
#pragma unroll
        for (int e = 0; e < 2; ++e)
            bv[nj2][e] = bias[fbase + wn + nj2 * 8 + ((lane & 3) << 1) + e] * 4.0f;

#pragma unroll
    for (int mi = 0; mi < 4; ++mi) {
        int m0 = mbase + wm + (mi << 4) + (lane >> 2);
#pragma unroll
        for (int half = 0; half < 2; ++half) {
            int g = m0 + half * 8;
            int n_img = g / OHW;
            int rem = g - n_img * OHW;
            float* ob = out + (size_t)n_img * FNO * OHW + rem;
#pragma unroll
            for (int nj2 = 0; nj2 < 4; ++nj2) {
#pragma unroll
                for (int e = 0; e < 2; ++e) {
                    int f = fbase + wn + nj2 * 8 + ((lane & 3) << 1) + e;
                    float v = acc[mi][nj2][half * 2 + e] * 0.25f + bv[nj2][e];
                    v = rintf(v);
                    v = fminf(127.0f, fmaxf(-128.0f, v));
                    ob[(size_t)f * OHW] = v;
                }
            }
        }
    }
}

// ---------------- host ----------------
extern "C" void kernel_launch(void* const* d_in, const int* in_sizes, int n_in,
                              void* d_out, int out_size) {
    const float* in_data = (const float*)d_in[0];
    const float* weight  = (const float*)d_in[1];
    const float* bias    = (const float*)d_in[2];
    float* out = (float*)d_out;

    cudaFuncSetAttribute(conv_mma_kernel, cudaFuncAttributeMaxDynamicSharedMemorySize,
                         SMEM_TOTAL);

    prep_kernel<<<QBLKS + WBLKS + HBLKS, 256>>>(in_data, weight);
    {
        dim3 grid(FNO / BN, MTILES);   // (4, 169) = 676 CTAs
        conv_mma_kernel<<<grid, 256, SMEM_TOTAL>>>(bias, out);
    }
}